// round 15
// baseline (speedup 1.0000x reference)
#include <cuda_runtime.h>

// SegmenterTensorFlow: windowed framing + overlap-add reconstruction.
// B=8, N=4194304, seg=1024, hop=512 -> NSEG=8191, out_len=N.
//
// d_out layout: X [B, NSEG, SEG] followed by x_rec [B, N].
//
// hop = seg/2 => each sample n (s0=n>>9, m=n&511) lies in exactly two segments:
//   X[b, s0,   m    ]  (invalid when s0 == NSEG)
//   X[b, s0-1, m+512]  (invalid when s0 == 0)
// x_rec[b,n] = x[b,n] * (v0*aw[m]*sw[m] + v1*aw[m+512]*sw[m+512]).
//
// R15: 256-bit memory ops (Blackwell LDG.256/STG.256 via .v8.b32) — the
// last untested mechanism. 8 floats/thread, one v8 load + three v8 stores;
// halves LSU wavefronts per byte vs the 128-bit variants. All addresses are
// 32B-aligned (i, m multiples of 8 floats). Known risk: register pressure
// (R2's 2x128-bit variant hit 58 regs / 41% occ and regressed); v8 differs
// in that the op count is actually halved, not doubled.

#define BB   8
#define NN   4194304u
#define SEG  1024u
#define HOP  512u
#define NSEG 8191u

struct f8 { float v[8]; };

__device__ __forceinline__ f8 ldg256(const float* p) {
    f8 r;
    asm volatile("ld.global.nc.v8.b32 {%0,%1,%2,%3,%4,%5,%6,%7}, [%8];"
                 : "=f"(r.v[0]), "=f"(r.v[1]), "=f"(r.v[2]), "=f"(r.v[3]),
                   "=f"(r.v[4]), "=f"(r.v[5]), "=f"(r.v[6]), "=f"(r.v[7])
                 : "l"(p));
    return r;
}

__device__ __forceinline__ void stg256(float* p, const f8& a) {
    asm volatile("st.global.v8.b32 [%0], {%1,%2,%3,%4,%5,%6,%7,%8};"
                 :: "l"(p),
                    "f"(a.v[0]), "f"(a.v[1]), "f"(a.v[2]), "f"(a.v[3]),
                    "f"(a.v[4]), "f"(a.v[5]), "f"(a.v[6]), "f"(a.v[7])
                 : "memory");
}

__global__ __launch_bounds__(256)
void seg_olap_kernel(const float* __restrict__ x,
                     const float* __restrict__ aw,
                     const float* __restrict__ sw,
                     float* __restrict__ Xout,
                     float* __restrict__ rec)
{
    unsigned t = blockIdx.x * blockDim.x + threadIdx.x;   // < 2^22
    unsigned i = t << 3;                                  // element index, < 2^25

    unsigned b  = i >> 22;                                // N = 2^22
    unsigned n  = i & (NN - 1u);
    unsigned m  = n & (HOP - 1u);                         // multiple of 8 -> 32B aligned
    unsigned s0 = n >> 9;

    const bool v0 = (s0 < NSEG);                          // segment s0, offset m
    const bool v1 = (s0 >= 1u);                           // segment s0-1, offset m+512

    f8 xv  = ldg256(x + i);
    f8 awl = ldg256(aw + m);
    f8 awh = ldg256(aw + m + HOP);

    // X writes first so awl/awh products don't extend window-register lifetime
    if (v0) {
        f8 lo;
        #pragma unroll
        for (int k = 0; k < 8; ++k) lo.v[k] = xv.v[k] * awl.v[k];
        stg256(Xout + (b * NSEG + s0) * SEG + m, lo);
    }
    if (v1) {
        f8 hi;
        #pragma unroll
        for (int k = 0; k < 8; ++k) hi.v[k] = xv.v[k] * awh.v[k];
        stg256(Xout + (b * NSEG + (s0 - 1u)) * SEG + (m + HOP), hi);
    }

    // rec weight: sw loaded late, consumed immediately (limits live range)
    f8 swl = ldg256(sw + m);
    f8 swh = ldg256(sw + m + HOP);
    const float w0 = v0 ? 1.0f : 0.0f;
    const float w1 = v1 ? 1.0f : 0.0f;
    f8 r;
    #pragma unroll
    for (int k = 0; k < 8; ++k)
        r.v[k] = xv.v[k] * (w0 * awl.v[k] * swl.v[k] + w1 * awh.v[k] * swh.v[k]);
    stg256(rec + i, r);
}

extern "C" void kernel_launch(void* const* d_in, const int* in_sizes, int n_in,
                              void* d_out, int out_size)
{
    const float* x  = (const float*)d_in[0];
    const float* aw = (const float*)d_in[1];
    const float* sw = (const float*)d_in[2];

    float* Xout = (float*)d_out;
    float* rec  = Xout + (size_t)BB * NSEG * SEG;

    const unsigned total_v8 = (BB * NN) / 8u;             // 4,194,304 (exact multiple)
    const unsigned threads = 256;
    const unsigned blocks = total_v8 / threads;           // 16384, no remainder

    seg_olap_kernel<<<blocks, threads>>>(x, aw, sw, Xout, rec);
}

// round 16
// speedup vs baseline: 1.0074x; 1.0074x over previous
#include <cuda_runtime.h>

// SegmenterTensorFlow: windowed framing + overlap-add reconstruction.
// B=8, N=4194304, seg=1024, hop=512 -> NSEG=8191, out_len=N.
//
// d_out layout: X [B, NSEG, SEG] followed by x_rec [B, N].
//
// hop = seg/2 => each sample n (s0=n>>9, m=n&511) lies in exactly two segments:
//   X[b, s0,   m    ]  (invalid when s0 == NSEG)
//   X[b, s0-1, m+512]  (invalid when s0 == 0)
// x_rec[b,n] = x[b,n] * (v0*aw[m]*sw[m] + v1*aw[m+512]*sw[m+512]).
//
// FINAL (== R9/R12, best measured: 81.41us bench / 78.5us kernel, 35 regs):
// flat 1D launch, 512-thread blocks, one float4 per thread, 32-bit index
// arithmetic, default cache ops.
//
// Fifteen rounds established the workload is hard-pinned at the machine's
// mixed-stream DRAM ceiling: 536.8 MB mandatory traffic (134 MB read +
// 402 MB write) at ~6.05 TB/s DRAM => ~78.5us kernel floor. Measured
// neutral: all cache policies (.cs/.wt/evict-last/fractional), 256-bit
// LDG/STG, phase-resident windows, launch geometry (128/256/512 threads,
// 1D/2D grids). Measured harmful: per-thread unrolling with duplicated
// window state (register pressure -> occupancy collapse, R2).

#define BB   8
#define NN   4194304u
#define SEG  1024u
#define HOP  512u
#define NSEG 8191u

__global__ __launch_bounds__(512)
void seg_olap_kernel(const float* __restrict__ x,
                     const float* __restrict__ aw,
                     const float* __restrict__ sw,
                     float* __restrict__ Xout,
                     float* __restrict__ rec)
{
    unsigned t = blockIdx.x * blockDim.x + threadIdx.x;   // < 2^23
    unsigned i = t << 2;                                  // element index, < 2^25

    unsigned b  = i >> 22;                                // N = 2^22
    unsigned n  = i & (NN - 1u);
    unsigned m  = n & (HOP - 1u);                         // mod-512 phase (vec-aligned)
    unsigned s0 = n >> 9;

    const bool v0 = (s0 < NSEG);                          // segment s0, offset m
    const bool v1 = (s0 >= 1u);                           // segment s0-1, offset m+512

    float4 xv  = *reinterpret_cast<const float4*>(x + i);
    float4 awl = *reinterpret_cast<const float4*>(aw + m);
    float4 awh = *reinterpret_cast<const float4*>(aw + m + HOP);
    float4 swl = *reinterpret_cast<const float4*>(sw + m);
    float4 swh = *reinterpret_cast<const float4*>(sw + m + HOP);

    // X writes (coalesced: consecutive n -> consecutive j within a segment row)
    if (v0) {
        float4 lo;
        lo.x = xv.x * awl.x; lo.y = xv.y * awl.y;
        lo.z = xv.z * awl.z; lo.w = xv.w * awl.w;
        unsigned off = (b * NSEG + s0) * SEG + m;         // < 2^26
        *reinterpret_cast<float4*>(Xout + off) = lo;
    }
    if (v1) {
        float4 hi;
        hi.x = xv.x * awh.x; hi.y = xv.y * awh.y;
        hi.z = xv.z * awh.z; hi.w = xv.w * awh.w;
        unsigned off = (b * NSEG + (s0 - 1u)) * SEG + (m + HOP);
        *reinterpret_cast<float4*>(Xout + off) = hi;
    }

    // overlap-add collapses to pointwise weight
    float w0 = v0 ? 1.0f : 0.0f;
    float w1 = v1 ? 1.0f : 0.0f;
    float4 r;
    r.x = xv.x * (w0 * awl.x * swl.x + w1 * awh.x * swh.x);
    r.y = xv.y * (w0 * awl.y * swl.y + w1 * awh.y * swh.y);
    r.z = xv.z * (w0 * awl.z * swl.z + w1 * awh.z * swh.z);
    r.w = xv.w * (w0 * awl.w * swl.w + w1 * awh.w * swh.w);
    *reinterpret_cast<float4*>(rec + i) = r;
}

extern "C" void kernel_launch(void* const* d_in, const int* in_sizes, int n_in,
                              void* d_out, int out_size)
{
    const float* x  = (const float*)d_in[0];
    const float* aw = (const float*)d_in[1];
    const float* sw = (const float*)d_in[2];

    float* Xout = (float*)d_out;
    float* rec  = Xout + (size_t)BB * NSEG * SEG;

    const unsigned total_vec4 = (BB * NN) / 4u;           // 8,388,608 (exact multiple)
    const unsigned threads = 512;
    const unsigned blocks = total_vec4 / threads;         // 16384, no remainder

    seg_olap_kernel<<<blocks, threads>>>(x, aw, sw, Xout, rec);
}